// round 1
// baseline (speedup 1.0000x reference)
#include <cuda_runtime.h>
#include <cuda_fp16.h>

// ---------------------------------------------------------------------------
// SparseBlock: 27-tap submanifold conv (gather-GEMM) + BatchNorm + LeakyReLU
//   out[n,:] = sum_k feats[nbr[n,k],:] @ W[k,:,:]    (nbr=-1 -> zero row)
//   y = (out - mean) * rsqrt(var + 1e-4) * gamma + beta ; leaky(0.333)
//
// Pipeline (all launched from kernel_launch, graph-capturable):
//   P1: feats fp32 -> fp16 scratch        (halves gather traffic)
//   P2: W     fp32 -> fp16 scratch
//   A : per-128-row-tile gathered GEMM via mma.sync m16n8k16 (f16 in, f32 acc)
//       + per-CTA per-channel sum / sumsq partials (deterministic, no atomics)
//   B : reduce partials -> scale/shift per channel
//   C : normalize + leaky, write d_out
// ---------------------------------------------------------------------------

#define N_TOT   262144
#define CIN     128
#define COUT    128
#define KTAPS   27
#define NBLK    (N_TOT / 128)        // 2048 row tiles

// shared memory layout (bytes) for conv kernel
#define AS_STRIDE 272                // 128 halves (256B) + 16B pad: ldmatrix conflict-free, 16B-aligned
#define AS_BYTES  (128 * AS_STRIDE)  // 34816
#define WS_OFF    AS_BYTES           // W tile, same geometry
#define IDX_OFF   (2 * AS_BYTES)     // 69632: rulebook slice, 128*27 ints = 13824B
#define SMEM_TOTAL (IDX_OFF + 128 * KTAPS * 4)   // 83456
#define OUTS_STRIDE 132              // fp32 out tile stride (floats), 16B-aligned rows

// ------------------------- device scratch (no mallocs) ---------------------
__device__ __half g_featsH[(size_t)N_TOT * CIN];          // 64 MB
__device__ __half g_WH[(size_t)KTAPS * CIN * COUT];       // 864 KB
__device__ float  g_conv[(size_t)N_TOT * COUT];           // 128 MB
__device__ float  g_psum[(size_t)COUT * NBLK];            // per (channel, tile)
__device__ float  g_psq [(size_t)COUT * NBLK];
__device__ float  g_scale[COUT];
__device__ float  g_shift[COUT];

// ------------------------------ PTX helpers --------------------------------
__device__ __forceinline__ void cp_async16(unsigned dst, const void* src, int szbytes) {
    asm volatile("cp.async.cg.shared.global [%0], [%1], 16, %2;\n"
                 :: "r"(dst), "l"(src), "r"(szbytes) : "memory");
}
__device__ __forceinline__ void cp_commit_wait() {
    asm volatile("cp.async.commit_group;\n" ::: "memory");
    asm volatile("cp.async.wait_group 0;\n" ::: "memory");
}
__device__ __forceinline__ void ldsm_x4(unsigned& a0, unsigned& a1, unsigned& a2, unsigned& a3,
                                        unsigned addr) {
    asm volatile("ldmatrix.sync.aligned.m8n8.x4.shared.b16 {%0,%1,%2,%3}, [%4];"
                 : "=r"(a0), "=r"(a1), "=r"(a2), "=r"(a3) : "r"(addr));
}
__device__ __forceinline__ void ldsm_x2t(unsigned& b0, unsigned& b1, unsigned addr) {
    asm volatile("ldmatrix.sync.aligned.m8n8.x2.trans.shared.b16 {%0,%1}, [%2];"
                 : "=r"(b0), "=r"(b1) : "r"(addr));
}
__device__ __forceinline__ void mma16816(float* c, unsigned a0, unsigned a1, unsigned a2,
                                         unsigned a3, unsigned b0, unsigned b1) {
    asm volatile(
        "mma.sync.aligned.m16n8k16.row.col.f32.f16.f16.f32 "
        "{%0,%1,%2,%3}, {%4,%5,%6,%7}, {%8,%9}, {%0,%1,%2,%3};"
        : "+f"(c[0]), "+f"(c[1]), "+f"(c[2]), "+f"(c[3])
        : "r"(a0), "r"(a1), "r"(a2), "r"(a3), "r"(b0), "r"(b1));
}

// ------------------------------ P1/P2: fp32->fp16 --------------------------
__global__ void prep_feats_kernel(const float* __restrict__ f) {
    int i = blockIdx.x * blockDim.x + threadIdx.x;       // over N*CIN/4 float4s
    float4 v = reinterpret_cast<const float4*>(f)[i];
    __half2* o = reinterpret_cast<__half2*>(g_featsH);
    o[2 * i]     = __floats2half2_rn(v.x, v.y);
    o[2 * i + 1] = __floats2half2_rn(v.z, v.w);
}
__global__ void prep_w_kernel(const float* __restrict__ w) {
    int i = blockIdx.x * blockDim.x + threadIdx.x;       // over K*CIN*COUT/4
    float4 v = reinterpret_cast<const float4*>(w)[i];
    __half2* o = reinterpret_cast<__half2*>(g_WH);
    o[2 * i]     = __floats2half2_rn(v.x, v.y);
    o[2 * i + 1] = __floats2half2_rn(v.z, v.w);
}

// ------------------------------ A: gathered GEMM ---------------------------
__global__ __launch_bounds__(256, 2) void conv_kernel(const int* __restrict__ nbr) {
    extern __shared__ char smem[];
    const int tid  = threadIdx.x;
    const int warp = tid >> 5;
    const int lane = tid & 31;
    const int b    = blockIdx.x;

    unsigned sA = (unsigned)__cvta_generic_to_shared(smem);
    unsigned sW = sA + WS_OFF;

    // load this tile's rulebook slice (128 rows x 27 taps), fully coalesced
    int* idxs = reinterpret_cast<int*>(smem + IDX_OFF);
    const int* nb = nbr + (size_t)b * 128 * KTAPS;
    #pragma unroll
    for (int i = tid; i < 128 * KTAPS; i += 256) idxs[i] = nb[i];
    __syncthreads();

    float acc[16][4];
    #pragma unroll
    for (int nt = 0; nt < 16; ++nt)
        #pragma unroll
        for (int j = 0; j < 4; ++j) acc[nt][j] = 0.f;

    const char* featsB = reinterpret_cast<const char*>(g_featsH);
    const char* wB     = reinterpret_cast<const char*>(g_WH);

    for (int k = 0; k < KTAPS; ++k) {
        // gather A tile: 128 rows x 256B fp16, cp.async 16B chunks, zero-fill invalid
        #pragma unroll
        for (int i = 0; i < 8; ++i) {
            int f = tid + i * 256;
            int r = f >> 4, u = f & 15;
            int idx = idxs[r * KTAPS + k];
            const char* gp = featsB + (size_t)(idx < 0 ? 0 : idx) * 256 + u * 16;
            cp_async16(sA + r * AS_STRIDE + u * 16, gp, idx < 0 ? 0 : 16);
        }
        // W[k] tile: 128 x 256B fp16
        const char* wk = wB + (size_t)k * CIN * COUT * 2;
        #pragma unroll
        for (int i = 0; i < 8; ++i) {
            int f = tid + i * 256;
            int r = f >> 4, u = f & 15;
            cp_async16(sW + r * AS_STRIDE + u * 16, wk + r * 256 + u * 16, 16);
        }
        cp_commit_wait();
        __syncthreads();

        // warp `warp` computes rows [warp*16, warp*16+16) x all 128 couts
        unsigned aBase = sA + (warp * 16 + (lane & 15)) * AS_STRIDE + (lane >> 4) * 16;
        #pragma unroll
        for (int ks = 0; ks < 8; ++ks) {             // 8 x k16 over CIN=128
            unsigned a0, a1, a2, a3;
            ldsm_x4(a0, a1, a2, a3, aBase + ks * 32);
            unsigned bAddr = sW + (ks * 16 + (lane & 15)) * AS_STRIDE;
            #pragma unroll
            for (int nt = 0; nt < 16; ++nt) {
                unsigned b0, b1;
                ldsm_x2t(b0, b1, bAddr + nt * 16);
                mma16816(acc[nt], a0, a1, a2, a3, b0, b1);
            }
        }
        __syncthreads();
    }

    // ---- epilogue: stage fp32 tile in shared (reuse A/W region) ----
    float* out_s = reinterpret_cast<float*>(smem);
    #pragma unroll
    for (int nt = 0; nt < 16; ++nt) {
        int col = nt * 8 + (lane & 3) * 2;
        int row = warp * 16 + (lane >> 2);
        *reinterpret_cast<float2*>(&out_s[row * OUTS_STRIDE + col]) =
            make_float2(acc[nt][0], acc[nt][1]);
        *reinterpret_cast<float2*>(&out_s[(row + 8) * OUTS_STRIDE + col]) =
            make_float2(acc[nt][2], acc[nt][3]);
    }
    __syncthreads();

    // per-channel partial sums over this tile's 128 rows
    {
        int col = tid & 127, hf = tid >> 7;
        float s = 0.f, sq = 0.f;
        int r0 = hf * 64;
        #pragma unroll 8
        for (int r = r0; r < r0 + 64; ++r) {
            float v = out_s[r * OUTS_STRIDE + col];
            s += v; sq += v * v;
        }
        float* red  = reinterpret_cast<float*>(smem + IDX_OFF);
        float* redq = red + 256;
        red[tid] = s; redq[tid] = sq;
        __syncthreads();
        if (tid < 128) {
            g_psum[(size_t)tid * NBLK + b] = red[tid] + red[tid + 128];
            g_psq [(size_t)tid * NBLK + b] = redq[tid] + redq[tid + 128];
        }
    }

    // coalesced store of conv result tile
    size_t gbase4 = (size_t)b * 4096;                 // float4 units
    float4* gout = reinterpret_cast<float4*>(g_conv);
    #pragma unroll
    for (int it = 0; it < 16; ++it) {
        int rr = (tid >> 5) + it * 8;
        int c4 = tid & 31;
        float4 v = *reinterpret_cast<float4*>(&out_s[rr * OUTS_STRIDE + c4 * 4]);
        gout[gbase4 + rr * 32 + c4] = v;
    }
}

// ------------------------------ B: BN stats --------------------------------
__global__ void reduce_kernel(const float* __restrict__ gamma,
                              const float* __restrict__ beta) {
    int c = blockIdx.x, t = threadIdx.x;
    float s = 0.f, sq = 0.f;
    for (int i = t; i < NBLK; i += 256) {
        s  += g_psum[(size_t)c * NBLK + i];
        sq += g_psq [(size_t)c * NBLK + i];
    }
    __shared__ float rs[256], rq[256];
    rs[t] = s; rq[t] = sq;
    __syncthreads();
    for (int o = 128; o > 0; o >>= 1) {
        if (t < o) { rs[t] += rs[t + o]; rq[t] += rq[t + o]; }
        __syncthreads();
    }
    if (t == 0) {
        float mean = rs[0] / (float)N_TOT;
        float var  = rq[0] / (float)N_TOT - mean * mean;
        float rstd = rsqrtf(var + 1e-4f);
        float sc   = rstd * gamma[c];
        g_scale[c] = sc;
        g_shift[c] = beta[c] - mean * sc;
    }
}

// ------------------------------ C: finalize --------------------------------
__global__ void finalize_kernel(float* __restrict__ out) {
    int i = blockIdx.x * blockDim.x + threadIdx.x;     // over N*COUT/4 float4s
    float4 v = reinterpret_cast<const float4*>(g_conv)[i];
    int c = (i & 31) * 4;
    float x;
    x = v.x * g_scale[c]     + g_shift[c];     v.x = x > 0.f ? x : 0.333f * x;
    x = v.y * g_scale[c + 1] + g_shift[c + 1]; v.y = x > 0.f ? x : 0.333f * x;
    x = v.z * g_scale[c + 2] + g_shift[c + 2]; v.z = x > 0.f ? x : 0.333f * x;
    x = v.w * g_scale[c + 3] + g_shift[c + 3]; v.w = x > 0.f ? x : 0.333f * x;
    reinterpret_cast<float4*>(out)[i] = v;
}

// ------------------------------ launch -------------------------------------
extern "C" void kernel_launch(void* const* d_in, const int* in_sizes, int n_in,
                              void* d_out, int out_size) {
    const float* feats = (const float*)d_in[0];
    const float* W     = (const float*)d_in[1];
    const float* gamma = (const float*)d_in[2];
    const float* beta  = (const float*)d_in[3];
    const int*   nbr   = (const int*)d_in[4];
    float* out = (float*)d_out;

    cudaFuncSetAttribute(conv_kernel, cudaFuncAttributeMaxDynamicSharedMemorySize,
                         SMEM_TOTAL);

    prep_feats_kernel<<<(N_TOT * CIN / 4) / 256, 256>>>(feats);
    prep_w_kernel<<<(KTAPS * CIN * COUT / 4) / 256, 256>>>(W);
    conv_kernel<<<NBLK, 256, SMEM_TOTAL>>>(nbr);
    reduce_kernel<<<COUT, 256>>>(gamma, beta);
    finalize_kernel<<<(N_TOT * COUT / 4) / 256, 256>>>(out);
}

// round 4
// speedup vs baseline: 1.1107x; 1.1107x over previous
#include <cuda_runtime.h>
#include <cuda_fp16.h>
#include <cstdint>

// ---------------------------------------------------------------------------
// SparseBlock: 27-tap submanifold conv (gather-GEMM) + BN + LeakyReLU
// Round 4 (= round 3 resubmit; prior failure was broker infra, not kernel):
//   * mma.sync HMMA (tcgen05 unavailable: harness ptxas targets base sm_100)
//   * M=256 rows/CTA, 2-stage cp.async double buffer (tap k+1 || compute k)
//   * 4x2 warp grid: each warp 64 rows x 64 cols -> smem reads 256KB/tap/CTA
//   * XOR-swizzled 256B rows, ldsm.x4 / ldsm.x4.trans, conflict-free
// ---------------------------------------------------------------------------

#define N_TOT   262144
#define CIN     128
#define COUT    128
#define KTAPS   27
#define MROWS   256
#define NBLK2   (N_TOT / MROWS)          // 1024 CTAs

#define A_BYTES     (MROWS * 256)        // 65536
#define W_BYTES     (128 * 256)          // 32768
#define STAGE_BYTES (A_BYTES + W_BYTES)  // 98304
#define W_OFF       A_BYTES
#define SM_IDX      (2 * STAGE_BYTES)    // 196608
#define IDX_INTS    (MROWS * KTAPS)      // 6912
#define SMEM_TOTAL  (SM_IDX + IDX_INTS * 4)  // 224256
#define STG_STRIDE  132                  // epilogue fp32 staging stride (floats)

// ------------------------- device scratch ----------------------------------
__device__ __half g_featsH[(size_t)N_TOT * CIN];          // 64 MB
__device__ __half g_WH[(size_t)KTAPS * CIN * COUT];       // [k][cin][cout] fp16
__device__ float  g_conv[(size_t)N_TOT * COUT];           // 128 MB
__device__ float  g_psum[(size_t)COUT * NBLK2];
__device__ float  g_psq [(size_t)COUT * NBLK2];
__device__ float  g_scale[COUT];
__device__ float  g_shift[COUT];

// ------------------------------ PTX helpers --------------------------------
__device__ __forceinline__ void cp_async16(unsigned dst, const void* src, int szbytes) {
    asm volatile("cp.async.cg.shared.global [%0], [%1], 16, %2;\n"
                 :: "r"(dst), "l"(src), "r"(szbytes) : "memory");
}
__device__ __forceinline__ void cp_commit() {
    asm volatile("cp.async.commit_group;\n" ::: "memory");
}
__device__ __forceinline__ void cp_wait1() {
    asm volatile("cp.async.wait_group 1;\n" ::: "memory");
}
__device__ __forceinline__ void cp_wait0() {
    asm volatile("cp.async.wait_group 0;\n" ::: "memory");
}
__device__ __forceinline__ void ldsm_x4(unsigned& a0, unsigned& a1, unsigned& a2,
                                        unsigned& a3, unsigned addr) {
    asm volatile("ldmatrix.sync.aligned.m8n8.x4.shared.b16 {%0,%1,%2,%3}, [%4];"
                 : "=r"(a0), "=r"(a1), "=r"(a2), "=r"(a3) : "r"(addr));
}
__device__ __forceinline__ void ldsm_x4t(unsigned& b0, unsigned& b1, unsigned& b2,
                                         unsigned& b3, unsigned addr) {
    asm volatile("ldmatrix.sync.aligned.m8n8.x4.trans.shared.b16 {%0,%1,%2,%3}, [%4];"
                 : "=r"(b0), "=r"(b1), "=r"(b2), "=r"(b3) : "r"(addr));
}
__device__ __forceinline__ void mma16816(float* c, unsigned a0, unsigned a1, unsigned a2,
                                         unsigned a3, unsigned b0, unsigned b1) {
    asm volatile(
        "mma.sync.aligned.m16n8k16.row.col.f32.f16.f16.f32 "
        "{%0,%1,%2,%3}, {%4,%5,%6,%7}, {%8,%9}, {%0,%1,%2,%3};"
        : "+f"(c[0]), "+f"(c[1]), "+f"(c[2]), "+f"(c[3])
        : "r"(a0), "r"(a1), "r"(a2), "r"(a3), "r"(b0), "r"(b1));
}

// XOR swizzle: 16B chunk u of row r lives at r*256 + (u ^ (r&7))*16.
// Keeps all ldsm phases (8 lanes x 16B) on 8 distinct 16B banks.
__device__ __forceinline__ unsigned swoff(int r, int u) {
    return (unsigned)(r * 256 + ((u ^ (r & 7)) << 4));
}

// ------------------------------ P1/P2: fp32->fp16 --------------------------
__global__ void prep_feats_kernel(const float* __restrict__ f) {
    int i = blockIdx.x * blockDim.x + threadIdx.x;
    float4 v = reinterpret_cast<const float4*>(f)[i];
    __half2* o = reinterpret_cast<__half2*>(g_featsH);
    o[2 * i]     = __floats2half2_rn(v.x, v.y);
    o[2 * i + 1] = __floats2half2_rn(v.z, v.w);
}
__global__ void prep_w_kernel(const float* __restrict__ w) {
    int i = blockIdx.x * blockDim.x + threadIdx.x;
    float4 v = reinterpret_cast<const float4*>(w)[i];
    __half2* o = reinterpret_cast<__half2*>(g_WH);
    o[2 * i]     = __floats2half2_rn(v.x, v.y);
    o[2 * i + 1] = __floats2half2_rn(v.z, v.w);
}

// ------------------------------ conv ---------------------------------------
__device__ __forceinline__ void load_tap(unsigned stg, const int* __restrict__ idxs,
                                         int k, int tid,
                                         const char* featsB, const char* wB) {
    const char* wk = wB + (size_t)k * (CIN * COUT * 2);
    #pragma unroll
    for (int i = 0; i < 8; ++i) {                      // W tile: 128 rows x 256B
        int id = tid + i * 256, r = id >> 4, u = id & 15;
        cp_async16(stg + W_OFF + swoff(r, u), wk + r * 256 + u * 16, 16);
    }
    #pragma unroll
    for (int i = 0; i < 16; ++i) {                     // A gather: 256 rows x 256B
        int id = tid + i * 256, r = id >> 4, u = id & 15;
        int idx = idxs[r * KTAPS + k];
        const char* src = featsB + (size_t)(idx < 0 ? 0 : idx) * 256 + u * 16;
        cp_async16(stg + swoff(r, u), src, idx < 0 ? 0 : 16);
    }
}

__global__ void __launch_bounds__(256, 1) conv_kernel(const int* __restrict__ nbr) {
    extern __shared__ char smem[];
    const int tid = threadIdx.x, warp = tid >> 5, lane = tid & 31;
    const int mw = warp >> 1, nw = warp & 1;           // 4 x 2 warp grid
    const int b = blockIdx.x;
    unsigned sbase = (unsigned)__cvta_generic_to_shared(smem);

    int* idxs = reinterpret_cast<int*>(smem + SM_IDX);
    const int* nb = nbr + (size_t)b * IDX_INTS;
    #pragma unroll
    for (int i = tid; i < IDX_INTS; i += 256) idxs[i] = nb[i];
    __syncthreads();

    float acc[4][8][4];                                 // 4 m16 x 8 n8 tiles
    #pragma unroll
    for (int t = 0; t < 4; ++t)
        #pragma unroll
        for (int j = 0; j < 8; ++j)
            #pragma unroll
            for (int q = 0; q < 4; ++q) acc[t][j][q] = 0.f;

    const char* featsB = reinterpret_cast<const char*>(g_featsH);
    const char* wB     = reinterpret_cast<const char*>(g_WH);

    load_tap(sbase, idxs, 0, tid, featsB, wB);
    cp_commit();

    #pragma unroll 1
    for (int k = 0; k < KTAPS; ++k) {
        unsigned stage = sbase + (unsigned)((k & 1) * STAGE_BYTES);
        if (k + 1 < KTAPS) {
            load_tap(sbase + (unsigned)(((k + 1) & 1) * STAGE_BYTES),
                     idxs, k + 1, tid, featsB, wB);
            cp_commit();
            cp_wait1();                                // tap k resident
        } else {
            cp_wait0();
        }
        __syncthreads();

        unsigned sA = stage, sW = stage + W_OFF;
        #pragma unroll
        for (int ks = 0; ks < 8; ++ks) {               // CIN in k16 steps
            unsigned a[4][4], bf[4][4];
            #pragma unroll
            for (int t = 0; t < 4; ++t) {
                int r = mw * 64 + t * 16 + (lane & 15);
                ldsm_x4(a[t][0], a[t][1], a[t][2], a[t][3],
                        sA + swoff(r, ks * 2 + (lane >> 4)));
            }
            #pragma unroll
            for (int j = 0; j < 4; ++j) {              // 4 n16 blocks of 64 cols
                int r = ks * 16 + (lane & 15);
                ldsm_x4t(bf[j][0], bf[j][1], bf[j][2], bf[j][3],
                         sW + swoff(r, nw * 8 + j * 2 + (lane >> 4)));
            }
            #pragma unroll
            for (int t = 0; t < 4; ++t)
                #pragma unroll
                for (int j = 0; j < 4; ++j) {
                    mma16816(acc[t][2 * j],     a[t][0], a[t][1], a[t][2], a[t][3],
                             bf[j][0], bf[j][1]);
                    mma16816(acc[t][2 * j + 1], a[t][0], a[t][1], a[t][2], a[t][3],
                             bf[j][2], bf[j][3]);
                }
        }
        __syncthreads();
    }

    // ---- epilogue: stage fp32 tile (256 x 128) in smem ----
    float* stg = reinterpret_cast<float*>(smem);
    #pragma unroll
    for (int t = 0; t < 4; ++t)
        #pragma unroll
        for (int j = 0; j < 8; ++j) {
            int row = mw * 64 + t * 16 + (lane >> 2);
            int col = nw * 64 + j * 8 + (lane & 3) * 2;
            *reinterpret_cast<float2*>(&stg[row * STG_STRIDE + col]) =
                make_float2(acc[t][j][0], acc[t][j][1]);
            *reinterpret_cast<float2*>(&stg[(row + 8) * STG_STRIDE + col]) =
                make_float2(acc[t][j][2], acc[t][j][3]);
        }
    __syncthreads();

    // per-channel partial sums over this tile's 256 rows (deterministic)
    {
        int col = tid & 127, part = tid >> 7;
        float s = 0.f, sq = 0.f;
        #pragma unroll 8
        for (int r = 0; r < 128; ++r) {
            float v = stg[(part * 128 + r) * STG_STRIDE + col];
            s += v; sq += v * v;
        }
        float* red  = reinterpret_cast<float*>(smem + SM_IDX);
        float* redq = red + 256;
        red[tid] = s; redq[tid] = sq;
        __syncthreads();
        if (tid < 128) {
            g_psum[(size_t)tid * NBLK2 + b] = red[tid] + red[tid + 128];
            g_psq [(size_t)tid * NBLK2 + b] = redq[tid] + redq[tid + 128];
        }
    }

    // coalesced fp32 store of the 256x128 tile
    float4* gout = reinterpret_cast<float4*>(g_conv);
    size_t gbase = (size_t)b * (MROWS * COUT / 4);
    #pragma unroll
    for (int it = 0; it < 32; ++it) {
        int id = tid + it * 256;
        int row = id >> 5, c4 = id & 31;
        float4 v = *reinterpret_cast<float4*>(&stg[row * STG_STRIDE + c4 * 4]);
        gout[gbase + row * 32 + c4] = v;
    }
}

// ------------------------------ BN stats -----------------------------------
__global__ void reduce_kernel(const float* __restrict__ gamma,
                              const float* __restrict__ beta) {
    int c = blockIdx.x, t = threadIdx.x;
    float s = 0.f, sq = 0.f;
    for (int i = t; i < NBLK2; i += 256) {
        s  += g_psum[(size_t)c * NBLK2 + i];
        sq += g_psq [(size_t)c * NBLK2 + i];
    }
    __shared__ float rs[256], rq[256];
    rs[t] = s; rq[t] = sq;
    __syncthreads();
    for (int o = 128; o > 0; o >>= 1) {
        if (t < o) { rs[t] += rs[t + o]; rq[t] += rq[t + o]; }
        __syncthreads();
    }
    if (t == 0) {
        float mean = rs[0] / (float)N_TOT;
        float var  = rq[0] / (float)N_TOT - mean * mean;
        float sc   = rsqrtf(var + 1e-4f) * gamma[c];
        g_scale[c] = sc;
        g_shift[c] = beta[c] - mean * sc;
    }
}

// ------------------------------ finalize -----------------------------------
__global__ void finalize_kernel(float* __restrict__ out) {
    int i = blockIdx.x * blockDim.x + threadIdx.x;
    float4 v = reinterpret_cast<const float4*>(g_conv)[i];
    int c = (i & 31) * 4;
    float x;
    x = v.x * g_scale[c]     + g_shift[c];     v.x = x > 0.f ? x : 0.333f * x;
    x = v.y * g_scale[c + 1] + g_shift[c + 1]; v.y = x > 0.f ? x : 0.333f * x;
    x = v.z * g_scale[c + 2] + g_shift[c + 2]; v.z = x > 0.f ? x : 0.333f * x;
    x = v.w * g_scale[c + 3] + g_shift[c + 3]; v.w = x > 0.f ? x : 0.333f * x;
    reinterpret_cast<float4*>(out)[i] = v;
}

// ------------------------------ launch -------------------------------------
extern "C" void kernel_launch(void* const* d_in, const int* in_sizes, int n_in,
                              void* d_out, int out_size) {
    const float* feats = (const float*)d_in[0];
    const float* W     = (const float*)d_in[1];
    const float* gamma = (const float*)d_in[2];
    const float* beta  = (const float*)d_in[3];
    const int*   nbr   = (const int*)d_in[4];
    float* out = (float*)d_out;

    cudaFuncSetAttribute(conv_kernel, cudaFuncAttributeMaxDynamicSharedMemorySize,
                         SMEM_TOTAL);

    prep_feats_kernel<<<(N_TOT * CIN / 4) / 256, 256>>>(feats);
    prep_w_kernel<<<(KTAPS * CIN * COUT / 4) / 256, 256>>>(W);
    conv_kernel<<<NBLK2, 256, SMEM_TOTAL>>>(nbr);
    reduce_kernel<<<COUT, 256>>>(gamma, beta);
    finalize_kernel<<<(N_TOT * COUT / 4) / 256, 256>>>(out);
}

// round 6
// speedup vs baseline: 1.3477x; 1.2134x over previous
#include <cuda_runtime.h>
#include <cuda_fp16.h>
#include <cstdint>

// ---------------------------------------------------------------------------
// SparseBlock: 27-tap submanifold conv + BN + LeakyReLU.
// Round 6 (= round 5 resubmit; failure was broker infra — same string as
// rounds 0/3, and round 3's kernel passed unchanged in round 4).
// Exploit sparsity: only ~15.7% of (row,tap) pairs are valid, and the legacy
// HMMA issue ceiling (rt~13cyc/SMSP, measured r1 vs r4) means fewer mma is
// the only lever.
//   rulebook_kernel: per 256-row tile, compact valid (in_idx,out_row) pairs
//                    per tap, padded to 32-row batches (dummy->dump row 256).
//   conv_kernel:     fp32 out tile in SMEM; stream 32-row batches:
//                    gather(cp.async, 3-stage) -> mma -> scatter-add.
//                    Column-partitioned warps => race-free, deterministic,
//                    bit-identical to dense tap-order sum.
// ---------------------------------------------------------------------------

#define N_TOT   262144
#define CIN     128
#define COUT    128
#define KTAPS   27
#define MROWS   256
#define NTILE   (N_TOT / MROWS)          // 1024 tiles
#define MAXP    (KTAPS * MROWS)          // 6912 pairs worst case (padded)
#define MAXB    (MAXP / 32)              // 216 batches worst case

// ---- conv SMEM layout (bytes) ----
#define OUT_STRIDE 132                   // floats; 257 rows (row 256 = dump)
#define OUT_FLOATS (257 * OUT_STRIDE)    // 33924
#define WOFF    136192                   // 1024-aligned, after out tile
#define AOFF    (WOFF + 2 * 32768)       // 201728, 3 x 8KB A batch buffers
#define POFF    (AOFF + 3 * 8192)        // 226304, 3 x 128B pair staging
#define OFSOFF  (POFF + 3 * 128)         // 226688, 28 ints
#define BTOFF   (OFSOFF + 112)           // 226800, btap[216] + bslot[216]
#define SMEM_TOTAL 227328

// ------------------------- device scratch ----------------------------------
__device__ __half g_featsH[(size_t)N_TOT * CIN];          // 64 MB
__device__ __half g_WH[(size_t)KTAPS * CIN * COUT];       // fp16 [k][cin][cout]
__device__ float  g_conv[(size_t)N_TOT * COUT];           // 128 MB
__device__ int    g_pairs[(size_t)NTILE * MAXP];          // 28.3 MB
__device__ int    g_tapofs[(size_t)NTILE * 28];           // pair-unit prefix
__device__ float  g_psum[(size_t)COUT * NTILE];
__device__ float  g_psq [(size_t)COUT * NTILE];
__device__ float  g_scale[COUT];
__device__ float  g_shift[COUT];

// ------------------------------ PTX helpers --------------------------------
__device__ __forceinline__ void cp_async16(unsigned dst, const void* src) {
    asm volatile("cp.async.cg.shared.global [%0], [%1], 16;\n"
                 :: "r"(dst), "l"(src) : "memory");
}
__device__ __forceinline__ void cp_commit() {
    asm volatile("cp.async.commit_group;\n" ::: "memory");
}
__device__ __forceinline__ void cp_wait1() {
    asm volatile("cp.async.wait_group 1;\n" ::: "memory");
}
__device__ __forceinline__ void cp_wait0() {
    asm volatile("cp.async.wait_group 0;\n" ::: "memory");
}
__device__ __forceinline__ void ldsm_x4(unsigned& a0, unsigned& a1, unsigned& a2,
                                        unsigned& a3, unsigned addr) {
    asm volatile("ldmatrix.sync.aligned.m8n8.x4.shared.b16 {%0,%1,%2,%3}, [%4];"
                 : "=r"(a0), "=r"(a1), "=r"(a2), "=r"(a3) : "r"(addr));
}
__device__ __forceinline__ void ldsm_x4t(unsigned& b0, unsigned& b1, unsigned& b2,
                                         unsigned& b3, unsigned addr) {
    asm volatile("ldmatrix.sync.aligned.m8n8.x4.trans.shared.b16 {%0,%1,%2,%3}, [%4];"
                 : "=r"(b0), "=r"(b1), "=r"(b2), "=r"(b3) : "r"(addr));
}
__device__ __forceinline__ void mma16816(float* c, unsigned a0, unsigned a1, unsigned a2,
                                         unsigned a3, unsigned b0, unsigned b1) {
    asm volatile(
        "mma.sync.aligned.m16n8k16.row.col.f32.f16.f16.f32 "
        "{%0,%1,%2,%3}, {%4,%5,%6,%7}, {%8,%9}, {%0,%1,%2,%3};"
        : "+f"(c[0]), "+f"(c[1]), "+f"(c[2]), "+f"(c[3])
        : "r"(a0), "r"(a1), "r"(a2), "r"(a3), "r"(b0), "r"(b1));
}
// XOR swizzle for 256B rows (conflict-free ldsm)
__device__ __forceinline__ unsigned swoff(int r, int u) {
    return (unsigned)(r * 256 + ((u ^ (r & 7)) << 4));
}

// ------------------------------ prep: fp32->fp16 ---------------------------
__global__ void prep_feats_kernel(const float* __restrict__ f) {
    int i = blockIdx.x * blockDim.x + threadIdx.x;
    float4 v = reinterpret_cast<const float4*>(f)[i];
    __half2* o = reinterpret_cast<__half2*>(g_featsH);
    o[2 * i]     = __floats2half2_rn(v.x, v.y);
    o[2 * i + 1] = __floats2half2_rn(v.z, v.w);
}
__global__ void prep_w_kernel(const float* __restrict__ w) {
    int i = blockIdx.x * blockDim.x + threadIdx.x;
    float4 v = reinterpret_cast<const float4*>(w)[i];
    __half2* o = reinterpret_cast<__half2*>(g_WH);
    o[2 * i]     = __floats2half2_rn(v.x, v.y);
    o[2 * i + 1] = __floats2half2_rn(v.z, v.w);
}

// ------------------------------ rulebook compaction ------------------------
__global__ void rulebook_kernel(const int* __restrict__ nbr) {
    __shared__ int snb[MROWS * KTAPS];                 // 27648 B
    __shared__ int warpcnt[8];
    const int tile = blockIdx.x, t = threadIdx.x;
    const int w = t >> 5, lane = t & 31;
    for (int i = t; i < MROWS * KTAPS; i += 256)
        snb[i] = nbr[(size_t)tile * (MROWS * KTAPS) + i];
    __syncthreads();

    int* pr = g_pairs + (size_t)tile * MAXP;
    int ofs = 0;                                       // identical in all threads
    for (int k = 0; k < KTAPS; ++k) {
        int idx = snb[t * KTAPS + k];                  // stride 27: conflict-free
        bool v = idx >= 0;
        unsigned m = __ballot_sync(0xFFFFFFFFu, v);
        if (lane == 0) warpcnt[w] = __popc(m);
        __syncthreads();
        int base = 0, total = 0;
        #pragma unroll
        for (int w2 = 0; w2 < 8; ++w2) {
            if (w2 < w) base += warpcnt[w2];
            total += warpcnt[w2];
        }
        if (v) pr[ofs + base + __popc(m & ((1u << lane) - 1))] = (idx << 9) | t;
        int padded = (total + 31) & ~31;
        for (int p = total + t; p < padded; p += 256)
            pr[ofs + p] = 256;                         // idx 0, dump row 256
        if (t == 0) g_tapofs[tile * 28 + k] = ofs;
        ofs += padded;
        __syncthreads();                               // warpcnt reuse
    }
    if (t == 0) g_tapofs[tile * 28 + 27] = ofs;
}

// ------------------------------ conv ---------------------------------------
__global__ void __launch_bounds__(256, 1) conv_kernel() {
    extern __shared__ char smem[];
    const int tid = threadIdx.x, warp = tid >> 5, lane = tid & 31;
    const int tile = blockIdx.x;
    unsigned sbase = (unsigned)__cvta_generic_to_shared(smem);

    float* outs = reinterpret_cast<float*>(smem);
    int* ofs_s = reinterpret_cast<int*>(smem + OFSOFF);
    unsigned char* btap  = reinterpret_cast<unsigned char*>(smem + BTOFF);
    unsigned char* bslot = btap + MAXB;

    // zero output tile (incl. dump row 256)
    float4* oz = reinterpret_cast<float4*>(outs);
    for (int i = tid; i < OUT_FLOATS / 4; i += 256)
        oz[i] = make_float4(0.f, 0.f, 0.f, 0.f);
    if (tid < 28) ofs_s[tid] = g_tapofs[tile * 28 + tid];
    __syncthreads();

    const int B = ofs_s[27] >> 5;                      // batches of 32 pairs
    for (int j = tid; j < B; j += 256) {
        int p = j * 32, k = 0;
        while (ofs_s[k + 1] <= p) k++;
        btap[j] = (unsigned char)k;
        int slot = 0;
        for (int q = 0; q < k; ++q) slot ^= (ofs_s[q + 1] > ofs_s[q]) ? 1 : 0;
        bslot[j] = (unsigned char)slot;
    }
    __syncthreads();

    const char* featsB = reinterpret_cast<const char*>(g_featsH);
    const char* wB     = reinterpret_cast<const char*>(g_WH);
    const int*  pbase  = g_pairs + (size_t)tile * MAXP;

    // ---- issue helpers (inlined) ----
    // gather batch jj into slot jj%3 (+ stage its 32 pairs)
    auto issue_batch = [&](int jj) {
        const int* pj = pbase + jj * 32;
        unsigned aslot = sbase + AOFF + (unsigned)((jj % 3) * 8192);
        if (tid < 8)
            cp_async16(sbase + POFF + (unsigned)((jj % 3) * 128 + tid * 16),
                       pj + tid * 4);
        #pragma unroll
        for (int s = 0; s < 2; ++s) {
            int id = tid + s * 256;
            int row = id >> 4, u = id & 15;
            int pr = __ldg(pj + row);
            cp_async16(aslot + swoff(row, u),
                       featsB + ((size_t)(pr >> 9)) * 256 + u * 16);
        }
    };
    auto issue_w = [&](int k, int slot) {
        const char* wk = wB + (size_t)k * 32768;
        unsigned wd = sbase + WOFF + (unsigned)(slot * 32768);
        #pragma unroll
        for (int s = 0; s < 8; ++s) {
            int id = tid + s * 256;
            int r = id >> 4, u = id & 15;
            cp_async16(wd + swoff(r, u), wk + r * 256 + u * 16);
        }
    };

    // prologue: W[first tap] + batch 0 in one group
    issue_w(btap[0], 0);
    issue_batch(0);
    cp_commit();

    #pragma unroll 1
    for (int j = 0; j < B; ++j) {
        if (j + 1 < B) {
            issue_batch(j + 1);
            cp_commit();
            cp_wait1();                                // batch j (and older W) done
        } else {
            cp_wait0();
        }
        __syncthreads();                               // data visible; buffers free
        if (j + 1 < B && btap[j + 1] != btap[j]) {     // post-sync W prefetch
            issue_w(btap[j + 1], bslot[j + 1]);
            cp_commit();
        }

        // ---- compute batch j ----
        unsigned sA = sbase + AOFF + (unsigned)((j % 3) * 8192);
        unsigned sW = sbase + WOFF + (unsigned)(bslot[j] * 32768);
        const int* bp = reinterpret_cast<const int*>(smem + POFF + (j % 3) * 128);

        float acc[2][2][4];
        #pragma unroll
        for (int tm = 0; tm < 2; ++tm)
            #pragma unroll
            for (int n = 0; n < 2; ++n)
                #pragma unroll
                for (int q = 0; q < 4; ++q) acc[tm][n][q] = 0.f;

        #pragma unroll
        for (int ks = 0; ks < 8; ++ks) {
            unsigned a0[4], a1[4], bf[4];
            ldsm_x4(a0[0], a0[1], a0[2], a0[3],
                    sA + swoff((lane & 15), ks * 2 + (lane >> 4)));
            ldsm_x4(a1[0], a1[1], a1[2], a1[3],
                    sA + swoff(16 + (lane & 15), ks * 2 + (lane >> 4)));
            ldsm_x4t(bf[0], bf[1], bf[2], bf[3],
                     sW + swoff(ks * 16 + (lane & 15), warp * 2 + (lane >> 4)));
            mma16816(acc[0][0], a0[0], a0[1], a0[2], a0[3], bf[0], bf[1]);
            mma16816(acc[0][1], a0[0], a0[1], a0[2], a0[3], bf[2], bf[3]);
            mma16816(acc[1][0], a1[0], a1[1], a1[2], a1[3], bf[0], bf[1]);
            mma16816(acc[1][1], a1[0], a1[1], a1[2], a1[3], bf[2], bf[3]);
        }

        // ---- scatter-add into out tile (warp owns 16 cols: race-free) ----
        #pragma unroll
        for (int tm = 0; tm < 2; ++tm) {
            int r0 = bp[tm * 16 + (lane >> 2)] & 511;
            int r1 = bp[tm * 16 + 8 + (lane >> 2)] & 511;
            #pragma unroll
            for (int n = 0; n < 2; ++n) {
                int col = warp * 16 + n * 8 + (lane & 3) * 2;
                float2* p0 = reinterpret_cast<float2*>(&outs[r0 * OUT_STRIDE + col]);
                float2 v0 = *p0; v0.x += acc[tm][n][0]; v0.y += acc[tm][n][1]; *p0 = v0;
                float2* p1 = reinterpret_cast<float2*>(&outs[r1 * OUT_STRIDE + col]);
                float2 v1 = *p1; v1.x += acc[tm][n][2]; v1.y += acc[tm][n][3]; *p1 = v1;
            }
        }
        __syncthreads();                               // batch done before reuse
    }

    // ---- BN partials (deterministic) ----
    {
        int col = tid & 127, part = tid >> 7;
        float s = 0.f, sq = 0.f;
        #pragma unroll 8
        for (int r = 0; r < 128; ++r) {
            float v = outs[(part * 128 + r) * OUT_STRIDE + col];
            s += v; sq += v * v;
        }
        float* red  = reinterpret_cast<float*>(smem + AOFF);   // A bufs free now
        float* redq = red + 256;
        red[tid] = s; redq[tid] = sq;
        __syncthreads();
        if (tid < 128) {
            g_psum[(size_t)tid * NTILE + tile] = red[tid] + red[tid + 128];
            g_psq [(size_t)tid * NTILE + tile] = redq[tid] + redq[tid + 128];
        }
    }

    // ---- coalesced store of the 256x128 fp32 tile ----
    float4* gout = reinterpret_cast<float4*>(g_conv);
    size_t gbase = (size_t)tile * (MROWS * COUT / 4);
    #pragma unroll
    for (int it = 0; it < 32; ++it) {
        int id = tid + it * 256;
        int row = id >> 5, c4 = id & 31;
        float4 v = *reinterpret_cast<float4*>(&outs[row * OUT_STRIDE + c4 * 4]);
        gout[gbase + row * 32 + c4] = v;
    }
}

// ------------------------------ BN stats -----------------------------------
__global__ void reduce_kernel(const float* __restrict__ gamma,
                              const float* __restrict__ beta) {
    int c = blockIdx.x, t = threadIdx.x;
    float s = 0.f, sq = 0.f;
    for (int i = t; i < NTILE; i += 256) {
        s  += g_psum[(size_t)c * NTILE + i];
        sq += g_psq [(size_t)c * NTILE + i];
    }
    __shared__ float rs[256], rq[256];
    rs[t] = s; rq[t] = sq;
    __syncthreads();
    for (int o = 128; o > 0; o >>= 1) {
        if (t < o) { rs[t] += rs[t + o]; rq[t] += rq[t + o]; }
        __syncthreads();
    }
    if (t == 0) {
        float mean = rs[0] / (float)N_TOT;
        float var  = rq[0] / (float)N_TOT - mean * mean;
        float sc   = rsqrtf(var + 1e-4f) * gamma[c];
        g_scale[c] = sc;
        g_shift[c] = beta[c] - mean * sc;
    }
}

// ------------------------------ finalize -----------------------------------
__global__ void finalize_kernel(float* __restrict__ out) {
    int i = blockIdx.x * blockDim.x + threadIdx.x;
    float4 v = reinterpret_cast<const float4*>(g_conv)[i];
    int c = (i & 31) * 4;
    float x;
    x = v.x * g_scale[c]     + g_shift[c];     v.x = x > 0.f ? x : 0.333f * x;
    x = v.y * g_scale[c + 1] + g_shift[c + 1]; v.y = x > 0.f ? x : 0.333f * x;
    x = v.z * g_scale[c + 2] + g_shift[c + 2]; v.z = x > 0.f ? x : 0.333f * x;
    x = v.w * g_scale[c + 3] + g_shift[c + 3]; v.w = x > 0.f ? x : 0.333f * x;
    reinterpret_cast<float4*>(out)[i] = v;
}

// ------------------------------ launch -------------------------------------
extern "C" void kernel_launch(void* const* d_in, const int* in_sizes, int n_in,
                              void* d_out, int out_size) {
    const float* feats = (const float*)d_in[0];
    const float* W     = (const float*)d_in[1];
    const float* gamma = (const float*)d_in[2];
    const float* beta  = (const float*)d_in[3];
    const int*   nbr   = (const int*)d_in[4];
    float* out = (float*)d_out;

    cudaFuncSetAttribute(conv_kernel, cudaFuncAttributeMaxDynamicSharedMemorySize,
                         SMEM_TOTAL);

    prep_feats_kernel<<<(N_TOT * CIN / 4) / 256, 256>>>(feats);
    prep_w_kernel<<<(KTAPS * CIN * COUT / 4) / 256, 256>>>(W);
    rulebook_kernel<<<NTILE, 256>>>(nbr);
    conv_kernel<<<NTILE, 256, SMEM_TOTAL>>>();
    reduce_kernel<<<COUT, 256>>>(gamma, beta);
    finalize_kernel<<<(N_TOT * COUT / 4) / 256, 256>>>(out);
}